// round 8
// baseline (speedup 1.0000x reference)
#include <cuda_runtime.h>
#include <cuda_bf16.h>
#include <math.h>
#include <stdint.h>

#define BATCH 262144
#define HID 512
#define NDIM 12
#define TRI 78
#define OUTC 79

typedef __nv_bfloat16 bf16;
typedef __nv_bfloat162 bf162;

// Packed operand layout: row-major, width 1024 bf16 per row.
// col offset for k: (k/32)*64 + (k%32) -> hi plane; +32 -> lo plane.
__device__ bf16 g_h1pk[(size_t)BATCH * 1024];   // 512 MB
__device__ bf16 g_w2pk[(size_t)HID * 1024];     // 1 MB   (rows = out-col n)
__device__ bf16 g_w3pk[(size_t)96 * 1024];      // 192 KB (rows n, zero-pad >=79)

#define SWZ(o) ((o) ^ (((o) >> 3) & 0x70))

__device__ __forceinline__ uint32_t smem_u32(const void* p) {
    uint32_t a;
    asm("{ .reg .u64 t; cvta.to.shared.u64 t, %1; cvt.u32.u64 %0, t; }"
        : "=r"(a) : "l"(p));
    return a;
}
__device__ __forceinline__ void cp16(uint32_t dst, const void* src) {
    asm volatile("cp.async.cg.shared.global [%0], [%1], 16;"
                 :: "r"(dst), "l"(src));
}
#define CP_COMMIT() asm volatile("cp.async.commit_group;" ::: "memory")
#define CP_WAIT(n)  asm volatile("cp.async.wait_group %0;" :: "n"(n) : "memory")

#define LDSM_X4(r0, r1, r2, r3, a)                                            \
    asm volatile("ldmatrix.sync.aligned.m8n8.x4.shared.b16 {%0,%1,%2,%3}, [%4];" \
                 : "=r"(r0), "=r"(r1), "=r"(r2), "=r"(r3) : "r"(a))
#define LDSM_X2(r0, r1, a)                                                    \
    asm volatile("ldmatrix.sync.aligned.m8n8.x2.shared.b16 {%0,%1}, [%2];"    \
                 : "=r"(r0), "=r"(r1) : "r"(a))
#define MMA_BF16(c, a, b)                                                     \
    asm volatile("mma.sync.aligned.m16n8k16.row.col.f32.bf16.bf16.f32 "       \
                 "{%0,%1,%2,%3}, {%4,%5,%6,%7}, {%8,%9}, {%0,%1,%2,%3};"      \
                 : "+f"((c)[0]), "+f"((c)[1]), "+f"((c)[2]), "+f"((c)[3])     \
                 : "r"((a)[0]), "r"((a)[1]), "r"((a)[2]), "r"((a)[3]),        \
                   "r"((b)[0]), "r"((b)[1]))

static __device__ __forceinline__ float softplusf(float v) {
    return (v > 20.f) ? v : log1pf(expf(v));
}
static __device__ __forceinline__ int pkoff(int k) {
    return ((k >> 5) << 6) + (k & 31);
}

// ---------------- weight converters (transpose + hi/lo split + pack) --------
__global__ __launch_bounds__(256) void conv_w2(const float* __restrict__ W2) {
    int t = blockIdx.x * 256 + threadIdx.x;        // < 512*512
    int n = t >> 9, k = t & 511;
    float v = W2[(size_t)k * HID + n];
    bf16 h = __float2bfloat16(v);
    size_t o = (size_t)n * 1024 + pkoff(k);
    g_w2pk[o] = h;
    g_w2pk[o + 32] = __float2bfloat16(v - __bfloat162float(h));
}
__global__ __launch_bounds__(256) void conv_w3(const float* __restrict__ W3) {
    int t = blockIdx.x * 256 + threadIdx.x;        // < 96*512
    int n = t >> 9, k = t & 511;
    float v = (n < OUTC) ? W3[(size_t)k * OUTC + n] : 0.f;
    bf16 h = __float2bfloat16(v);
    size_t o = (size_t)n * 1024 + pkoff(k);
    g_w3pk[o] = h;
    g_w3pk[o + 32] = __float2bfloat16(v - __bfloat162float(h));
}

// ---------------- layer 1 (K=12) — vectorized 16B stores --------------------
__global__ __launch_bounds__(256) void l1_kernel(
    const float* __restrict__ x, const float* __restrict__ W1,
    const float* __restrict__ b1, bf16* __restrict__ hpk)
{
    __shared__ float W1s[NDIM][HID];
    __shared__ float b1s[HID];
    __shared__ float xs[64][13];
    const int tid = threadIdx.x;
    const int b0 = blockIdx.x * 64;

    for (int i = tid; i < NDIM * HID; i += 256) W1s[i / HID][i % HID] = W1[i];
    for (int i = tid; i < HID; i += 256) b1s[i] = b1[i];
    for (int i = tid; i < 64 * NDIM; i += 256)
        xs[i / NDIM][i % NDIM] = x[(size_t)b0 * NDIM + i];
    __syncthreads();

#pragma unroll 4
    for (int it = 0; it < 16; ++it) {
        int p = tid + it * 256;
        int r = p >> 6;
        int c = (p & 63) * 8;
        float a[8];
#pragma unroll
        for (int j = 0; j < 8; ++j) a[j] = b1s[c + j];
#pragma unroll
        for (int k = 0; k < NDIM; ++k) {
            float xv = xs[r][k];
#pragma unroll
            for (int j = 0; j < 8; ++j)
                a[j] = fmaf(xv, W1s[k][c + j], a[j]);
        }
        __align__(16) bf162 hb[4], lb[4];
#pragma unroll
        for (int j = 0; j < 4; ++j) {
            float v0 = fmaxf(a[2 * j], 0.f), v1 = fmaxf(a[2 * j + 1], 0.f);
            bf16 h0 = __float2bfloat16(v0), h1 = __float2bfloat16(v1);
            hb[j] = __halves2bfloat162(h0, h1);
            lb[j] = __halves2bfloat162(
                __float2bfloat16(v0 - __bfloat162float(h0)),
                __float2bfloat16(v1 - __bfloat162float(h1)));
        }
        size_t base = (size_t)(b0 + r) * 1024 + pkoff(c);
        *(uint4*)(hpk + base)      = *(uint4*)hb;
        *(uint4*)(hpk + base + 32) = *(uint4*)lb;
    }
}

// ---------------------------------------------------------------------------
// Fused GEMM2 + GEMM3: per CTA m-tile of 128 rows.
// For j=0..3: stage-1 computes h2 chunk (128 x 128) = relu(h1 @ W2[:,j]+b2)
// via 16 k-chunks (double-buffered cp.async), converts to packed hi/lo bf16
// in SMEM, then stage-2 accumulates C3 += h2chunk @ W3[jchunk]^T.
// Final: softplus + L@L^T + c.
// smem: A dbuf [0,32K), B2 dbuf [32K,64K), h2 [64K,128K), W3 dbuf [128K,224K)
// ---------------------------------------------------------------------------
__global__ __launch_bounds__(512, 1) void fused23(
    const bf16* __restrict__ Apk, const bf16* __restrict__ W2pk,
    const bf16* __restrict__ W3pk, const float* __restrict__ bias2,
    const float* __restrict__ bias3, float* __restrict__ dst)
{
    extern __shared__ char smem[];
    const uint32_t sb = smem_u32(smem);
    constexpr int OFF_B = 32768;
    constexpr int OFF_H = 65536;
    constexpr int OFF_W3 = 131072;
    constexpr int W3SZ = 49152;

    const int tid = threadIdx.x;
    const int lane = tid & 31;
    const int wid = tid >> 5;
    const int wm = wid >> 2;        // 0..3, m band of 32
    const int wn = wid & 3;         // 0..3, n band of 32 (stage1) / 24 (stage2)
    const int m0 = blockIdx.x * 128;

    float acc2[2][4][4];
    float acc3[2][3][4];
#pragma unroll
    for (int i = 0; i < 2; i++) {
#pragma unroll
        for (int j = 0; j < 4; j++)
#pragma unroll
            for (int k = 0; k < 4; k++) acc2[i][j][k] = 0.f;
#pragma unroll
        for (int j = 0; j < 3; j++)
#pragma unroll
            for (int k = 0; k < 4; k++) acc3[i][j][k] = 0.f;
    }

    const bf16* Abase = Apk + (size_t)m0 * 1024;

    auto load_chunk = [&](int j, int c, int buf) {
        uint32_t ab = sb + buf * 16384;
        uint32_t bb = sb + OFF_B + buf * 16384;
        const bf16* As = Abase + c * 64;
        const bf16* Bs = W2pk + (size_t)(j * 128) * 1024 + c * 64;
#pragma unroll
        for (int it = 0; it < 4; ++it) {
            int u = tid + it * 512;              // 0..2047
            int half = u >> 10;
            int v = u & 1023;
            int r = v >> 3, q = v & 7;
            const bf16* s = (half ? Bs : As) + (size_t)r * 1024 + q * 8;
            cp16((half ? bb : ab) + SWZ(r * 128 + q * 16), s);
        }
        CP_COMMIT();
    };

    auto load_w3 = [&](int j) {
        uint32_t wb = sb + OFF_W3 + (j & 1) * W3SZ;
        const bf16* Ws = W3pk + j * 256;
#pragma unroll
        for (int it = 0; it < 6; ++it) {
            int u = tid + it * 512;              // 0..3071
            int sub = u / 768;
            int v = u - sub * 768;
            int r = v >> 3, q = v & 7;
            cp16(wb + sub * 12288 + SWZ(r * 128 + q * 16),
                 Ws + (size_t)r * 1024 + sub * 64 + q * 8);
        }
        CP_COMMIT();
    };

    load_chunk(0, 0, 0);
    load_w3(0);

    for (int j = 0; j < 4; ++j) {
        // ---- stage 1: 16 k-chunks into acc2 ----
        for (int c = 0; c < 16; ++c) {
            CP_WAIT(0);
            __syncthreads();
            if (c < 15) load_chunk(j, c + 1, (c + 1) & 1);

            const int buf = c & 1;
            const uint32_t ab = sb + buf * 16384;
            const uint32_t bb = sb + OFF_B + buf * 16384;

#pragma unroll
            for (int ks = 0; ks < 2; ++ks) {
                uint32_t bfr[2][4][2];
                const int brow0 = wn * 32 + (lane & 7);
                const int bsel = (lane >> 3) & 1;
#pragma unroll
                for (int pl = 0; pl < 2; ++pl)
#pragma unroll
                    for (int nt = 0; nt < 4; ++nt) {
                        int row = brow0 + nt * 8;
                        int seg = pl * 4 + ks * 2 + bsel;
                        LDSM_X2(bfr[pl][nt][0], bfr[pl][nt][1],
                                bb + row * 128 + ((seg ^ (row & 7)) << 4));
                    }
#pragma unroll
                for (int mt = 0; mt < 2; ++mt) {
                    uint32_t afr[2][4];
                    const int arow = wm * 32 + mt * 16 + (lane & 15);
                    const int asel = lane >> 4;
#pragma unroll
                    for (int pl = 0; pl < 2; ++pl) {
                        int seg = pl * 4 + ks * 2 + asel;
                        LDSM_X4(afr[pl][0], afr[pl][1], afr[pl][2], afr[pl][3],
                                ab + arow * 128 + ((seg ^ (arow & 7)) << 4));
                    }
#pragma unroll
                    for (int nt = 0; nt < 4; ++nt)
                        MMA_BF16(acc2[mt][nt], afr[0], bfr[0][nt]);   // hi*hi
#pragma unroll
                    for (int nt = 0; nt < 4; ++nt)
                        MMA_BF16(acc2[mt][nt], afr[0], bfr[1][nt]);   // hi*lo
#pragma unroll
                    for (int nt = 0; nt < 4; ++nt)
                        MMA_BF16(acc2[mt][nt], afr[1], bfr[0][nt]);   // lo*hi
                }
            }
        }

        // ---- convert acc2 -> packed hi/lo h2 chunk in smem; reset acc2 ----
        {
            const int r0 = wm * 32 + (lane >> 2);
            const int c0 = wn * 32 + (lane & 3) * 2;
#pragma unroll
            for (int mt = 0; mt < 2; ++mt)
#pragma unroll
                for (int nt = 0; nt < 4; ++nt) {
                    const int col = c0 + nt * 8;
                    const int gcol = j * 128 + col;
                    const float bb0 = __ldg(bias2 + gcol);
                    const float bb1 = __ldg(bias2 + gcol + 1);
                    const int ci = col >> 5, kin = col & 31;
                    char* base = smem + OFF_H + ci * 16384;
#pragma unroll
                    for (int h = 0; h < 2; ++h) {
                        const int row = r0 + mt * 16 + 8 * h;
                        float v0 = fmaxf(acc2[mt][nt][2 * h] + bb0, 0.f);
                        float v1 = fmaxf(acc2[mt][nt][2 * h + 1] + bb1, 0.f);
                        bf16 h0 = __float2bfloat16(v0), h1 = __float2bfloat16(v1);
                        bf16 l0 = __float2bfloat16(v0 - __bfloat162float(h0));
                        bf16 l1 = __float2bfloat16(v1 - __bfloat162float(h1));
                        *(bf162*)(base + SWZ(row * 128 + kin * 2)) =
                            __halves2bfloat162(h0, h1);
                        *(bf162*)(base + SWZ(row * 128 + 64 + kin * 2)) =
                            __halves2bfloat162(l0, l1);
                        acc2[mt][nt][2 * h] = 0.f;
                        acc2[mt][nt][2 * h + 1] = 0.f;
                    }
                }
        }
        __syncthreads();   // h2 chunk visible to all warps

        // prefetch next j's first chunk + W3 slice (buffers free / double-buf)
        if (j < 3) { load_chunk(j + 1, 0, 0); load_w3(j + 1); }

        // ---- stage 2: acc3 += h2chunk @ W3[j]^T ----
        const uint32_t w3b = sb + OFF_W3 + (j & 1) * W3SZ;
#pragma unroll
        for (int sub = 0; sub < 4; ++sub) {
            const uint32_t ab = sb + OFF_H + sub * 16384;
            const uint32_t bb = w3b + sub * 12288;
#pragma unroll
            for (int ks = 0; ks < 2; ++ks) {
                uint32_t bfr[2][3][2];
                const int brow0 = wn * 24 + (lane & 7);
                const int bsel = (lane >> 3) & 1;
#pragma unroll
                for (int pl = 0; pl < 2; ++pl)
#pragma unroll
                    for (int nt = 0; nt < 3; ++nt) {
                        int row = brow0 + nt * 8;
                        int seg = pl * 4 + ks * 2 + bsel;
                        LDSM_X2(bfr[pl][nt][0], bfr[pl][nt][1],
                                bb + row * 128 + ((seg ^ (row & 7)) << 4));
                    }
#pragma unroll
                for (int mt = 0; mt < 2; ++mt) {
                    uint32_t afr[2][4];
                    const int arow = wm * 32 + mt * 16 + (lane & 15);
                    const int asel = lane >> 4;
#pragma unroll
                    for (int pl = 0; pl < 2; ++pl) {
                        int seg = pl * 4 + ks * 2 + asel;
                        LDSM_X4(afr[pl][0], afr[pl][1], afr[pl][2], afr[pl][3],
                                ab + arow * 128 + ((seg ^ (arow & 7)) << 4));
                    }
#pragma unroll
                    for (int nt = 0; nt < 3; ++nt)
                        MMA_BF16(acc3[mt][nt], afr[0], bfr[0][nt]);
#pragma unroll
                    for (int nt = 0; nt < 3; ++nt)
                        MMA_BF16(acc3[mt][nt], afr[0], bfr[1][nt]);
#pragma unroll
                    for (int nt = 0; nt < 3; ++nt)
                        MMA_BF16(acc3[mt][nt], afr[1], bfr[0][nt]);
                }
            }
        }
        // next iteration's first __syncthreads() protects h2 reuse
    }

    __syncthreads();
    // ---- final epilogue: softplus -> stage (pitch 81) -> L@L^T + c ----
    float* stage = (float*)smem;     // reuse A/B region (41 KB needed)
    {
        const int r0 = wm * 32 + (lane >> 2);
        const int c0 = wn * 24 + (lane & 3) * 2;
#pragma unroll
        for (int mt = 0; mt < 2; ++mt)
#pragma unroll
            for (int nt = 0; nt < 3; ++nt) {
                const int col = c0 + nt * 8;
                if (col >= 80) continue;
#pragma unroll
                for (int h = 0; h < 2; ++h) {
                    const int row = r0 + mt * 16 + 8 * h;
                    if (col < OUTC)
                        stage[row * 81 + col] =
                            softplusf(acc3[mt][nt][2 * h] + __ldg(bias3 + col));
                    if (col + 1 < OUTC)
                        stage[row * 81 + col + 1] =
                            softplusf(acc3[mt][nt][2 * h + 1] + __ldg(bias3 + col + 1));
                }
            }
    }
    __syncthreads();

    {
        const int r = tid >> 2;          // 0..127
        const int q = tid & 3;
        const float* Lr = stage + r * 81;
        float* drow = dst + ((size_t)(m0 + r)) * 144;
#pragma unroll
        for (int ii = 0; ii < 12; ++ii) {
            if ((ii & 3) != q) continue;
            const float* Li = Lr + ((ii * (ii + 1)) >> 1);
#pragma unroll
            for (int kk = 0; kk <= ii; ++kk) {
                const float* Lk = Lr + ((kk * (kk + 1)) >> 1);
                float a = 0.f;
#pragma unroll
                for (int jx = 0; jx <= kk; ++jx) a = fmaf(Li[jx], Lk[jx], a);
                drow[ii * 12 + kk] = a;
                if (kk != ii) drow[kk * 12 + ii] = a;
            }
        }
        if (tid < 128)
            dst[(size_t)BATCH * 144 + m0 + tid] = stage[tid * 81 + TRI];
    }
}

// ---------------- launch ----------------------------------------------------
extern "C" void kernel_launch(void* const* d_in, const int* in_sizes, int n_in,
                              void* d_out, int out_size)
{
    const float* x  = (const float*)d_in[0];
    const float* W1 = (const float*)d_in[1];
    const float* b1 = (const float*)d_in[2];
    const float* W2 = (const float*)d_in[3];
    const float* b2 = (const float*)d_in[4];
    const float* W3 = (const float*)d_in[5];
    const float* b3 = (const float*)d_in[6];
    float* out = (float*)d_out;

    bf16 *h1pk, *w2pk, *w3pk;
    cudaGetSymbolAddress((void**)&h1pk, g_h1pk);
    cudaGetSymbolAddress((void**)&w2pk, g_w2pk);
    cudaGetSymbolAddress((void**)&w3pk, g_w3pk);

    conv_w2<<<(HID * HID) / 256, 256>>>(W2);
    conv_w3<<<(96 * HID) / 256, 256>>>(W3);
    l1_kernel<<<BATCH / 64, 256>>>(x, W1, b1, h1pk);

    constexpr int SMEM_F = 131072 + 2 * 49152;   // 229376
    cudaFuncSetAttribute(fused23,
                         cudaFuncAttributeMaxDynamicSharedMemorySize, SMEM_F);

    fused23<<<BATCH / 128, 512, SMEM_F>>>(h1pk, w2pk, w3pk, b2, b3, out);
}

// round 9
// speedup vs baseline: 1.0826x; 1.0826x over previous
#include <cuda_runtime.h>
#include <cuda_bf16.h>
#include <math.h>
#include <stdint.h>

#define BATCH 262144
#define HID 512
#define NDIM 12
#define TRI 78
#define OUTC 79

typedef __nv_bfloat16 bf16;
typedef __nv_bfloat162 bf162;

// Packed operand layout: row-major, width 1024 bf16 per row.
// col offset for k: (k/32)*64 + (k%32) -> hi plane; +32 -> lo plane.
__device__ bf16 g_h1pk[(size_t)BATCH * 1024];   // 512 MB
__device__ bf16 g_h2pk[(size_t)BATCH * 1024];   // 512 MB
__device__ bf16 g_w2pk[(size_t)HID * 1024];     // 1 MB   (rows = out-col n)
__device__ bf16 g_w3pk[(size_t)96 * 1024];      // 192 KB (rows n, zero-pad >=79)

#define SWZ(o) ((o) ^ (((o) >> 3) & 0x70))

__device__ __forceinline__ uint32_t smem_u32(const void* p) {
    uint32_t a;
    asm("{ .reg .u64 t; cvta.to.shared.u64 t, %1; cvt.u32.u64 %0, t; }"
        : "=r"(a) : "l"(p));
    return a;
}
__device__ __forceinline__ void cp16(uint32_t dst, const void* src) {
    asm volatile("cp.async.cg.shared.global [%0], [%1], 16;"
                 :: "r"(dst), "l"(src));
}
#define CP_COMMIT() asm volatile("cp.async.commit_group;" ::: "memory")
#define CP_WAIT(n)  asm volatile("cp.async.wait_group %0;" :: "n"(n) : "memory")

#define LDSM_X4(r0, r1, r2, r3, a)                                            \
    asm volatile("ldmatrix.sync.aligned.m8n8.x4.shared.b16 {%0,%1,%2,%3}, [%4];" \
                 : "=r"(r0), "=r"(r1), "=r"(r2), "=r"(r3) : "r"(a))
#define LDSM_X2(r0, r1, a)                                                    \
    asm volatile("ldmatrix.sync.aligned.m8n8.x2.shared.b16 {%0,%1}, [%2];"    \
                 : "=r"(r0), "=r"(r1) : "r"(a))
#define MMA_BF16(c, a, b)                                                     \
    asm volatile("mma.sync.aligned.m16n8k16.row.col.f32.bf16.bf16.f32 "       \
                 "{%0,%1,%2,%3}, {%4,%5,%6,%7}, {%8,%9}, {%0,%1,%2,%3};"      \
                 : "+f"((c)[0]), "+f"((c)[1]), "+f"((c)[2]), "+f"((c)[3])     \
                 : "r"((a)[0]), "r"((a)[1]), "r"((a)[2]), "r"((a)[3]),        \
                   "r"((b)[0]), "r"((b)[1]))

static __device__ __forceinline__ float softplusf(float v) {
    return (v > 20.f) ? v : log1pf(expf(v));
}
static __device__ __forceinline__ int pkoff(int k) {
    return ((k >> 5) << 6) + (k & 31);
}

// ---------------- weight converters (transpose + hi/lo split + pack) --------
__global__ __launch_bounds__(256) void conv_w2(const float* __restrict__ W2) {
    int t = blockIdx.x * 256 + threadIdx.x;        // < 512*512
    int n = t >> 9, k = t & 511;
    float v = W2[(size_t)k * HID + n];
    bf16 h = __float2bfloat16(v);
    size_t o = (size_t)n * 1024 + pkoff(k);
    g_w2pk[o] = h;
    g_w2pk[o + 32] = __float2bfloat16(v - __bfloat162float(h));
}
__global__ __launch_bounds__(256) void conv_w3(const float* __restrict__ W3) {
    int t = blockIdx.x * 256 + threadIdx.x;        // < 96*512
    int n = t >> 9, k = t & 511;
    float v = (n < OUTC) ? W3[(size_t)k * OUTC + n] : 0.f;
    bf16 h = __float2bfloat16(v);
    size_t o = (size_t)n * 1024 + pkoff(k);
    g_w3pk[o] = h;
    g_w3pk[o + 32] = __float2bfloat16(v - __bfloat162float(h));
}

// ---------------- layer 1 (K=12) — vectorized 16B stores --------------------
__global__ __launch_bounds__(256) void l1_kernel(
    const float* __restrict__ x, const float* __restrict__ W1,
    const float* __restrict__ b1, bf16* __restrict__ hpk)
{
    __shared__ float W1s[NDIM][HID];
    __shared__ float b1s[HID];
    __shared__ float xs[64][13];
    const int tid = threadIdx.x;
    const int b0 = blockIdx.x * 64;

    for (int i = tid; i < NDIM * HID; i += 256) W1s[i / HID][i % HID] = W1[i];
    for (int i = tid; i < HID; i += 256) b1s[i] = b1[i];
    for (int i = tid; i < 64 * NDIM; i += 256)
        xs[i / NDIM][i % NDIM] = x[(size_t)b0 * NDIM + i];
    __syncthreads();

#pragma unroll 4
    for (int it = 0; it < 16; ++it) {
        int p = tid + it * 256;
        int r = p >> 6;
        int c = (p & 63) * 8;
        float a[8];
#pragma unroll
        for (int j = 0; j < 8; ++j) a[j] = b1s[c + j];
#pragma unroll
        for (int k = 0; k < NDIM; ++k) {
            float xv = xs[r][k];
#pragma unroll
            for (int j = 0; j < 8; ++j)
                a[j] = fmaf(xv, W1s[k][c + j], a[j]);
        }
        __align__(16) bf162 hb[4], lb[4];
#pragma unroll
        for (int j = 0; j < 4; ++j) {
            float v0 = fmaxf(a[2 * j], 0.f), v1 = fmaxf(a[2 * j + 1], 0.f);
            bf16 h0 = __float2bfloat16(v0), h1 = __float2bfloat16(v1);
            hb[j] = __halves2bfloat162(h0, h1);
            lb[j] = __halves2bfloat162(
                __float2bfloat16(v0 - __bfloat162float(h0)),
                __float2bfloat16(v1 - __bfloat162float(h1)));
        }
        size_t base = (size_t)(b0 + r) * 1024 + pkoff(c);
        *(uint4*)(hpk + base)      = *(uint4*)hb;
        *(uint4*)(hpk + base + 32) = *(uint4*)lb;
    }
}

// ---------------- GEMM2 (R3-proven): relu(h1 @ W2^T + b2) -> packed h2 ------
__global__ __launch_bounds__(256, 2) void gemm2(
    const bf16* __restrict__ Apk, const bf16* __restrict__ Bpk,
    const float* __restrict__ bias, bf16* __restrict__ Opk)
{
    extern __shared__ char smem[];
    const uint32_t sb = smem_u32(smem);
    const int tid = threadIdx.x;
    const int lane = tid & 31;
    const int wid = tid >> 5;
    const int wm = wid >> 2;
    const int wn = wid & 3;
    const int m0 = blockIdx.y * 128;
    const int n0 = blockIdx.x * 128;

    float acc[4][4][4];
#pragma unroll
    for (int i = 0; i < 4; i++)
#pragma unroll
        for (int j = 0; j < 4; j++)
#pragma unroll
            for (int k = 0; k < 4; k++) acc[i][j][k] = 0.f;

    const bf16* Abase = Apk + (size_t)m0 * 1024;
    const bf16* Bbase = Bpk + (size_t)n0 * 1024;

    auto load_chunk = [&](int c, int buf) {
        uint32_t ab = sb + (buf ? 16384 : 0);
        uint32_t bb = sb + 32768 + (buf ? 16384 : 0);
        const bf16* As = Abase + c * 64;
        const bf16* Bs = Bbase + c * 64;
#pragma unroll
        for (int it = 0; it < 8; ++it) {
            int u = tid + it * 256;
            int half = u >> 10;
            int v = u & 1023;
            int r = v >> 3, q = v & 7;
            const bf16* s = (half ? Bs : As) + (size_t)r * 1024 + q * 8;
            cp16((half ? bb : ab) + SWZ(r * 128 + q * 16), s);
        }
        CP_COMMIT();
    };

    load_chunk(0, 0);

    for (int c = 0; c < 16; ++c) {
        CP_WAIT(0);
        __syncthreads();
        if (c < 15) load_chunk(c + 1, (c + 1) & 1);

        const int buf = c & 1;
        const uint32_t ab = sb + (buf ? 16384 : 0);
        const uint32_t bb = sb + 32768 + (buf ? 16384 : 0);

#pragma unroll
        for (int ks = 0; ks < 2; ++ks) {
            uint32_t bfr[2][4][2];
            const int brow0 = wn * 32 + (lane & 7);
            const int bsel = (lane >> 3) & 1;
#pragma unroll
            for (int pl = 0; pl < 2; ++pl)
#pragma unroll
                for (int nt = 0; nt < 4; ++nt) {
                    int row = brow0 + nt * 8;
                    int seg = pl * 4 + ks * 2 + bsel;
                    LDSM_X2(bfr[pl][nt][0], bfr[pl][nt][1],
                            bb + row * 128 + ((seg ^ (row & 7)) << 4));
                }
#pragma unroll
            for (int mt = 0; mt < 4; ++mt) {
                uint32_t afr[2][4];
                const int arow = wm * 64 + mt * 16 + (lane & 15);
                const int asel = lane >> 4;
#pragma unroll
                for (int pl = 0; pl < 2; ++pl) {
                    int seg = pl * 4 + ks * 2 + asel;
                    LDSM_X4(afr[pl][0], afr[pl][1], afr[pl][2], afr[pl][3],
                            ab + arow * 128 + ((seg ^ (arow & 7)) << 4));
                }
#pragma unroll
                for (int nt = 0; nt < 4; ++nt)
                    MMA_BF16(acc[mt][nt], afr[0], bfr[0][nt]);   // hi*hi
#pragma unroll
                for (int nt = 0; nt < 4; ++nt)
                    MMA_BF16(acc[mt][nt], afr[0], bfr[1][nt]);   // hi*lo
#pragma unroll
                for (int nt = 0; nt < 4; ++nt)
                    MMA_BF16(acc[mt][nt], afr[1], bfr[0][nt]);   // lo*hi
            }
        }
        __syncthreads();
    }

    const int r0 = wm * 64 + (lane >> 2);
    const int c0 = wn * 32 + (lane & 3) * 2;
#pragma unroll
    for (int mt = 0; mt < 4; ++mt)
#pragma unroll
        for (int nt = 0; nt < 4; ++nt) {
            const int gc = n0 + c0 + nt * 8;
            const float bb0 = __ldg(bias + gc);
            const float bb1 = __ldg(bias + gc + 1);
#pragma unroll
            for (int h = 0; h < 2; ++h) {
                const int row = m0 + r0 + mt * 16 + 8 * h;
                float v0 = fmaxf(acc[mt][nt][2 * h] + bb0, 0.f);
                float v1 = fmaxf(acc[mt][nt][2 * h + 1] + bb1, 0.f);
                bf16 h0 = __float2bfloat16(v0), h1 = __float2bfloat16(v1);
                bf16 l0 = __float2bfloat16(v0 - __bfloat162float(h0));
                bf16 l1 = __float2bfloat16(v1 - __bfloat162float(h1));
                size_t off = (size_t)row * 1024 + pkoff(gc);
                *(bf162*)(Opk + off)      = __halves2bfloat162(h0, h1);
                *(bf162*)(Opk + off + 32) = __halves2bfloat162(l0, l1);
            }
        }
}

// ---------------- GEMM3: N-tile 96, K-chunk 64, fused softplus + L@L^T + c --
// smem: A0@0(32K), A1@32K, B0@64K(24K), B1@88K; total 112K (x2 CTAs = 224K).
__global__ __launch_bounds__(256, 2) void gemm3_mmt(
    const bf16* __restrict__ Apk, const bf16* __restrict__ Bpk,
    const float* __restrict__ bias, float* __restrict__ dst)
{
    extern __shared__ char smem[];
    const uint32_t sb = smem_u32(smem);
    const int tid = threadIdx.x;
    const int lane = tid & 31;
    const int wid = tid >> 5;
    const int wm = wid >> 2;        // 0..1 (m band of 64)
    const int wn = wid & 3;         // 0..3 (n band of 24)
    const int m0 = blockIdx.y * 128;

    float acc[4][3][4];
#pragma unroll
    for (int i = 0; i < 4; i++)
#pragma unroll
        for (int j = 0; j < 3; j++)
#pragma unroll
            for (int k = 0; k < 4; k++) acc[i][j][k] = 0.f;

    const bf16* Abase = Apk + (size_t)m0 * 1024;

    // k64 chunk: A = 128 rows x 256B (two 128B sub-chunks), B = 96 rows x 256B
    auto load_chunk = [&](int c, int buf) {
        uint32_t ab = sb + buf * 32768;
        uint32_t bb = sb + 65536 + buf * 24576;
        const bf16* As = Abase + c * 128;
        const bf16* Bs = Bpk + c * 128;
#pragma unroll
        for (int it = 0; it < 14; ++it) {
            int u = tid + it * 256;              // 0..3583
            if (u < 2048) {                      // A: 128 rows x 16 units
                int r = u >> 4, q = u & 15;
                int sub = q >> 3, qi = q & 7;
                cp16(ab + sub * 16384 + SWZ(r * 128 + qi * 16),
                     As + (size_t)r * 1024 + sub * 64 + qi * 8);
            } else {                             // B: 96 rows x 16 units
                int v = u - 2048;
                int r = v >> 4, q = v & 15;
                int sub = q >> 3, qi = q & 7;
                cp16(bb + sub * 12288 + SWZ(r * 128 + qi * 16),
                     Bs + (size_t)r * 1024 + sub * 64 + qi * 8);
            }
        }
        CP_COMMIT();
    };

    load_chunk(0, 0);

    for (int c = 0; c < 8; ++c) {
        CP_WAIT(0);
        __syncthreads();
        if (c < 7) load_chunk(c + 1, (c + 1) & 1);

        const int buf = c & 1;
#pragma unroll
        for (int sub = 0; sub < 2; ++sub) {
            const uint32_t ab = sb + buf * 32768 + sub * 16384;
            const uint32_t bb = sb + 65536 + buf * 24576 + sub * 12288;
#pragma unroll
            for (int ks = 0; ks < 2; ++ks) {
                uint32_t bfr[2][3][2];
                const int brow0 = wn * 24 + (lane & 7);
                const int bsel = (lane >> 3) & 1;
#pragma unroll
                for (int pl = 0; pl < 2; ++pl)
#pragma unroll
                    for (int nt = 0; nt < 3; ++nt) {
                        int row = brow0 + nt * 8;
                        int seg = pl * 4 + ks * 2 + bsel;
                        LDSM_X2(bfr[pl][nt][0], bfr[pl][nt][1],
                                bb + row * 128 + ((seg ^ (row & 7)) << 4));
                    }
#pragma unroll
                for (int mt = 0; mt < 4; ++mt) {
                    uint32_t afr[2][4];
                    const int arow = wm * 64 + mt * 16 + (lane & 15);
                    const int asel = lane >> 4;
#pragma unroll
                    for (int pl = 0; pl < 2; ++pl) {
                        int seg = pl * 4 + ks * 2 + asel;
                        LDSM_X4(afr[pl][0], afr[pl][1], afr[pl][2], afr[pl][3],
                                ab + arow * 128 + ((seg ^ (arow & 7)) << 4));
                    }
#pragma unroll
                    for (int nt = 0; nt < 3; ++nt)
                        MMA_BF16(acc[mt][nt], afr[0], bfr[0][nt]);
#pragma unroll
                    for (int nt = 0; nt < 3; ++nt)
                        MMA_BF16(acc[mt][nt], afr[0], bfr[1][nt]);
#pragma unroll
                    for (int nt = 0; nt < 3; ++nt)
                        MMA_BF16(acc[mt][nt], afr[1], bfr[0][nt]);
                }
            }
        }
        __syncthreads();
    }

    // ---- epilogue: softplus -> smem stage (pitch 81) ----
    const int r0 = wm * 64 + (lane >> 2);
    const int c0 = wn * 24 + (lane & 3) * 2;
    float* stage = (float*)smem;
#pragma unroll
    for (int mt = 0; mt < 4; ++mt)
#pragma unroll
        for (int nt = 0; nt < 3; ++nt) {
            const int col = c0 + nt * 8;
            if (col >= 80) continue;
#pragma unroll
            for (int h = 0; h < 2; ++h) {
                const int row = r0 + mt * 16 + 8 * h;
                if (col < OUTC)
                    stage[row * 81 + col] =
                        softplusf(acc[mt][nt][2 * h] + __ldg(bias + col));
                if (col + 1 < OUTC)
                    stage[row * 81 + col + 1] =
                        softplusf(acc[mt][nt][2 * h + 1] + __ldg(bias + col + 1));
            }
        }
    __syncthreads();

    // ---- symmetric L@L^T: 2 threads per row, fully unrolled, no div ----
    {
        const int r = tid >> 1;
        const int half = tid & 1;
        const float* Lr = stage + r * 81;
        float* drow = dst + ((size_t)(m0 + r)) * 144;
#pragma unroll
        for (int ii = 0; ii < 12; ++ii) {
            if (((ii ^ half) & 1) == 0) continue;   // split rows by ii parity
            const float* Li = Lr + ((ii * (ii + 1)) >> 1);
#pragma unroll
            for (int kk = 0; kk <= ii; ++kk) {
                const float* Lk = Lr + ((kk * (kk + 1)) >> 1);
                float a = 0.f;
#pragma unroll
                for (int j = 0; j <= kk; ++j) a = fmaf(Li[j], Lk[j], a);
                drow[ii * 12 + kk] = a;
                if (kk != ii) drow[kk * 12 + ii] = a;
            }
        }
        if (tid < 128)
            dst[(size_t)BATCH * 144 + m0 + tid] = stage[tid * 81 + TRI];
    }
}

// ---------------- launch ----------------------------------------------------
extern "C" void kernel_launch(void* const* d_in, const int* in_sizes, int n_in,
                              void* d_out, int out_size)
{
    const float* x  = (const float*)d_in[0];
    const float* W1 = (const float*)d_in[1];
    const float* b1 = (const float*)d_in[2];
    const float* W2 = (const float*)d_in[3];
    const float* b2 = (const float*)d_in[4];
    const float* W3 = (const float*)d_in[5];
    const float* b3 = (const float*)d_in[6];
    float* out = (float*)d_out;

    bf16 *h1pk, *h2pk, *w2pk, *w3pk;
    cudaGetSymbolAddress((void**)&h1pk, g_h1pk);
    cudaGetSymbolAddress((void**)&h2pk, g_h2pk);
    cudaGetSymbolAddress((void**)&w2pk, g_w2pk);
    cudaGetSymbolAddress((void**)&w3pk, g_w3pk);

    conv_w2<<<(HID * HID) / 256, 256>>>(W2);
    conv_w3<<<(96 * HID) / 256, 256>>>(W3);
    l1_kernel<<<BATCH / 64, 256>>>(x, W1, b1, h1pk);

    constexpr int SMEM2 = 65536;
    constexpr int SMEM3 = 114688;        // 2x(32K A + 24K B)
    cudaFuncSetAttribute(gemm2,
                         cudaFuncAttributeMaxDynamicSharedMemorySize, SMEM2);
    cudaFuncSetAttribute(gemm3_mmt,
                         cudaFuncAttributeMaxDynamicSharedMemorySize, SMEM3);

    gemm2<<<dim3(4, BATCH / 128), 256, SMEM2>>>(h1pk, w2pk, b2, h2pk);
    gemm3_mmt<<<dim3(1, BATCH / 128), 256, SMEM3>>>(h2pk, w3pk, b3, out);
}

// round 10
// speedup vs baseline: 1.1974x; 1.1060x over previous
#include <cuda_runtime.h>
#include <cuda_bf16.h>
#include <math.h>
#include <stdint.h>

#define BATCH 262144
#define HID 512
#define NDIM 12
#define TRI 78
#define OUTC 79

typedef __nv_bfloat16 bf16;
typedef __nv_bfloat162 bf162;

// h1: packed hi/lo rows 1024 wide: (k/32)*64 + k%32 (hi), +32 (lo).
// h2: plain bf16 rows 512 wide (hi only).
// W2: packed hi/lo rows 1024 wide (rows = out-col n).
// W3: packed hi/lo rows 1024 wide (rows n, zero-pad >= 79).
__device__ bf16 g_h1pk[(size_t)BATCH * 1024];   // 512 MB
__device__ bf16 g_h2pk[(size_t)BATCH * 512];    // 256 MB
__device__ bf16 g_w2pk[(size_t)HID * 1024];     // 1 MB
__device__ bf16 g_w3pk[(size_t)96 * 1024];      // 192 KB

#define SWZ(o) ((o) ^ (((o) >> 3) & 0x70))

__device__ __forceinline__ uint32_t smem_u32(const void* p) {
    uint32_t a;
    asm("{ .reg .u64 t; cvta.to.shared.u64 t, %1; cvt.u32.u64 %0, t; }"
        : "=r"(a) : "l"(p));
    return a;
}
__device__ __forceinline__ void cp16(uint32_t dst, const void* src) {
    asm volatile("cp.async.cg.shared.global [%0], [%1], 16;"
                 :: "r"(dst), "l"(src));
}
#define CP_COMMIT() asm volatile("cp.async.commit_group;" ::: "memory")
#define CP_WAIT(n)  asm volatile("cp.async.wait_group %0;" :: "n"(n) : "memory")

#define LDSM_X4(r0, r1, r2, r3, a)                                            \
    asm volatile("ldmatrix.sync.aligned.m8n8.x4.shared.b16 {%0,%1,%2,%3}, [%4];" \
                 : "=r"(r0), "=r"(r1), "=r"(r2), "=r"(r3) : "r"(a))
#define LDSM_X2(r0, r1, a)                                                    \
    asm volatile("ldmatrix.sync.aligned.m8n8.x2.shared.b16 {%0,%1}, [%2];"    \
                 : "=r"(r0), "=r"(r1) : "r"(a))
#define MMA_BF16(c, a, b)                                                     \
    asm volatile("mma.sync.aligned.m16n8k16.row.col.f32.bf16.bf16.f32 "       \
                 "{%0,%1,%2,%3}, {%4,%5,%6,%7}, {%8,%9}, {%0,%1,%2,%3};"      \
                 : "+f"((c)[0]), "+f"((c)[1]), "+f"((c)[2]), "+f"((c)[3])     \
                 : "r"((a)[0]), "r"((a)[1]), "r"((a)[2]), "r"((a)[3]),        \
                   "r"((b)[0]), "r"((b)[1]))

static __device__ __forceinline__ float softplusf(float v) {
    return (v > 20.f) ? v : log1pf(expf(v));
}
static __device__ __forceinline__ int pkoff(int k) {
    return ((k >> 5) << 6) + (k & 31);
}

// ---------------- weight converters ----------------------------------------
__global__ __launch_bounds__(256) void conv_w2(const float* __restrict__ W2) {
    int t = blockIdx.x * 256 + threadIdx.x;        // < 512*512
    int n = t >> 9, k = t & 511;
    float v = W2[(size_t)k * HID + n];
    bf16 h = __float2bfloat16(v);
    size_t o = (size_t)n * 1024 + pkoff(k);
    g_w2pk[o] = h;
    g_w2pk[o + 32] = __float2bfloat16(v - __bfloat162float(h));
}
__global__ __launch_bounds__(256) void conv_w3(const float* __restrict__ W3) {
    int t = blockIdx.x * 256 + threadIdx.x;        // < 96*512
    int n = t >> 9, k = t & 511;
    float v = (n < OUTC) ? W3[(size_t)k * OUTC + n] : 0.f;
    bf16 h = __float2bfloat16(v);
    size_t o = (size_t)n * 1024 + pkoff(k);
    g_w3pk[o] = h;
    g_w3pk[o + 32] = __float2bfloat16(v - __bfloat162float(h));
}

// ---------------- layer 1 (K=12) — vectorized 16B stores --------------------
__global__ __launch_bounds__(256) void l1_kernel(
    const float* __restrict__ x, const float* __restrict__ W1,
    const float* __restrict__ b1, bf16* __restrict__ hpk)
{
    __shared__ float W1s[NDIM][HID];
    __shared__ float b1s[HID];
    __shared__ float xs[64][13];
    const int tid = threadIdx.x;
    const int b0 = blockIdx.x * 64;

    for (int i = tid; i < NDIM * HID; i += 256) W1s[i / HID][i % HID] = W1[i];
    for (int i = tid; i < HID; i += 256) b1s[i] = b1[i];
    for (int i = tid; i < 64 * NDIM; i += 256)
        xs[i / NDIM][i % NDIM] = x[(size_t)b0 * NDIM + i];
    __syncthreads();

#pragma unroll 4
    for (int it = 0; it < 16; ++it) {
        int p = tid + it * 256;
        int r = p >> 6;
        int c = (p & 63) * 8;
        float a[8];
#pragma unroll
        for (int j = 0; j < 8; ++j) a[j] = b1s[c + j];
#pragma unroll
        for (int k = 0; k < NDIM; ++k) {
            float xv = xs[r][k];
#pragma unroll
            for (int j = 0; j < 8; ++j)
                a[j] = fmaf(xv, W1s[k][c + j], a[j]);
        }
        __align__(16) bf162 hb[4], lb[4];
#pragma unroll
        for (int j = 0; j < 4; ++j) {
            float v0 = fmaxf(a[2 * j], 0.f), v1 = fmaxf(a[2 * j + 1], 0.f);
            bf16 h0 = __float2bfloat16(v0), h1 = __float2bfloat16(v1);
            hb[j] = __halves2bfloat162(h0, h1);
            lb[j] = __halves2bfloat162(
                __float2bfloat16(v0 - __bfloat162float(h0)),
                __float2bfloat16(v1 - __bfloat162float(h1)));
        }
        size_t base = (size_t)(b0 + r) * 1024 + pkoff(c);
        *(uint4*)(hpk + base)      = *(uint4*)hb;
        *(uint4*)(hpk + base + 32) = *(uint4*)lb;
    }
}

// ---------------- GEMM2: relu(h1 @ W2^T + b2) -> plain bf16 h2 --------------
__global__ __launch_bounds__(256, 2) void gemm2(
    const bf16* __restrict__ Apk, const bf16* __restrict__ Bpk,
    const float* __restrict__ bias, bf16* __restrict__ Opk)
{
    extern __shared__ char smem[];
    const uint32_t sb = smem_u32(smem);
    const int tid = threadIdx.x;
    const int lane = tid & 31;
    const int wid = tid >> 5;
    const int wm = wid >> 2;
    const int wn = wid & 3;
    const int m0 = blockIdx.y * 128;
    const int n0 = blockIdx.x * 128;

    float acc[4][4][4];
#pragma unroll
    for (int i = 0; i < 4; i++)
#pragma unroll
        for (int j = 0; j < 4; j++)
#pragma unroll
            for (int k = 0; k < 4; k++) acc[i][j][k] = 0.f;

    const bf16* Abase = Apk + (size_t)m0 * 1024;
    const bf16* Bbase = Bpk + (size_t)n0 * 1024;

    auto load_chunk = [&](int c, int buf) {
        uint32_t ab = sb + (buf ? 16384 : 0);
        uint32_t bb = sb + 32768 + (buf ? 16384 : 0);
        const bf16* As = Abase + c * 64;
        const bf16* Bs = Bbase + c * 64;
#pragma unroll
        for (int it = 0; it < 8; ++it) {
            int u = tid + it * 256;
            int half = u >> 10;
            int v = u & 1023;
            int r = v >> 3, q = v & 7;
            const bf16* s = (half ? Bs : As) + (size_t)r * 1024 + q * 8;
            cp16((half ? bb : ab) + SWZ(r * 128 + q * 16), s);
        }
        CP_COMMIT();
    };

    load_chunk(0, 0);

    for (int c = 0; c < 16; ++c) {
        CP_WAIT(0);
        __syncthreads();
        if (c < 15) load_chunk(c + 1, (c + 1) & 1);

        const int buf = c & 1;
        const uint32_t ab = sb + (buf ? 16384 : 0);
        const uint32_t bb = sb + 32768 + (buf ? 16384 : 0);

#pragma unroll
        for (int ks = 0; ks < 2; ++ks) {
            uint32_t bfr[2][4][2];
            const int brow0 = wn * 32 + (lane & 7);
            const int bsel = (lane >> 3) & 1;
#pragma unroll
            for (int pl = 0; pl < 2; ++pl)
#pragma unroll
                for (int nt = 0; nt < 4; ++nt) {
                    int row = brow0 + nt * 8;
                    int seg = pl * 4 + ks * 2 + bsel;
                    LDSM_X2(bfr[pl][nt][0], bfr[pl][nt][1],
                            bb + row * 128 + ((seg ^ (row & 7)) << 4));
                }
#pragma unroll
            for (int mt = 0; mt < 4; ++mt) {
                uint32_t afr[2][4];
                const int arow = wm * 64 + mt * 16 + (lane & 15);
                const int asel = lane >> 4;
#pragma unroll
                for (int pl = 0; pl < 2; ++pl) {
                    int seg = pl * 4 + ks * 2 + asel;
                    LDSM_X4(afr[pl][0], afr[pl][1], afr[pl][2], afr[pl][3],
                            ab + arow * 128 + ((seg ^ (arow & 7)) << 4));
                }
#pragma unroll
                for (int nt = 0; nt < 4; ++nt)
                    MMA_BF16(acc[mt][nt], afr[0], bfr[0][nt]);   // hi*hi
#pragma unroll
                for (int nt = 0; nt < 4; ++nt)
                    MMA_BF16(acc[mt][nt], afr[0], bfr[1][nt]);   // hi*lo
#pragma unroll
                for (int nt = 0; nt < 4; ++nt)
                    MMA_BF16(acc[mt][nt], afr[1], bfr[0][nt]);   // lo*hi
            }
        }
        __syncthreads();
    }

    // epilogue: relu -> plain bf16 h2 (rows 512 wide)
    const int r0 = wm * 64 + (lane >> 2);
    const int c0 = wn * 32 + (lane & 3) * 2;
#pragma unroll
    for (int mt = 0; mt < 4; ++mt)
#pragma unroll
        for (int nt = 0; nt < 4; ++nt) {
            const int gc = n0 + c0 + nt * 8;
            const float bb0 = __ldg(bias + gc);
            const float bb1 = __ldg(bias + gc + 1);
#pragma unroll
            for (int h = 0; h < 2; ++h) {
                const int row = m0 + r0 + mt * 16 + 8 * h;
                float v0 = fmaxf(acc[mt][nt][2 * h] + bb0, 0.f);
                float v1 = fmaxf(acc[mt][nt][2 * h + 1] + bb1, 0.f);
                *(bf162*)(Opk + (size_t)row * 512 + gc) =
                    __halves2bfloat162(__float2bfloat16(v0), __float2bfloat16(v1));
            }
        }
}

// ---------------- GEMM3: A = plain bf16 h2, B = split W3; N-tile 96 ---------
// 2-term MMA (Ahi*Bhi + Ahi*Blo). K-chunk 64.
// smem: A0@0(16K), A1@16K, B0@32K(24K), B1@56K; total 80K (x2 CTAs = 160K).
__global__ __launch_bounds__(256, 2) void gemm3_mmt(
    const bf16* __restrict__ A, const bf16* __restrict__ Bpk,
    const float* __restrict__ bias, float* __restrict__ dst)
{
    extern __shared__ char smem[];
    const uint32_t sb = smem_u32(smem);
    const int tid = threadIdx.x;
    const int lane = tid & 31;
    const int wid = tid >> 5;
    const int wm = wid >> 2;        // 0..1 (m band of 64)
    const int wn = wid & 3;         // 0..3 (n band of 24)
    const int m0 = blockIdx.y * 128;

    float acc[4][3][4];
#pragma unroll
    for (int i = 0; i < 4; i++)
#pragma unroll
        for (int j = 0; j < 3; j++)
#pragma unroll
            for (int k = 0; k < 4; k++) acc[i][j][k] = 0.f;

    const bf16* Abase = A + (size_t)m0 * 512;

    // k64 chunk: A = 128 rows x 128B (plain), B = 96 rows x 256B (2 sub32)
    auto load_chunk = [&](int c, int buf) {
        uint32_t ab = sb + buf * 16384;
        uint32_t bb = sb + 32768 + buf * 24576;
        const bf16* As = Abase + c * 64;
        const bf16* Bs = Bpk + c * 128;
#pragma unroll
        for (int it = 0; it < 10; ++it) {
            int u = tid + it * 256;              // 0..2559
            if (u < 1024) {                      // A: 128 rows x 8 units
                int r = u >> 3, q = u & 7;
                cp16(ab + SWZ(r * 128 + q * 16), As + (size_t)r * 512 + q * 8);
            } else {                             // B: 96 rows x 16 units
                int v = u - 1024;
                int r = v >> 4, q = v & 15;
                int sub = q >> 3, qi = q & 7;
                cp16(bb + sub * 12288 + SWZ(r * 128 + qi * 16),
                     Bs + (size_t)r * 1024 + sub * 64 + qi * 8);
            }
        }
        CP_COMMIT();
    };

    load_chunk(0, 0);

    for (int c = 0; c < 8; ++c) {
        CP_WAIT(0);
        __syncthreads();
        if (c < 7) load_chunk(c + 1, (c + 1) & 1);

        const int buf = c & 1;
        const uint32_t ab = sb + buf * 16384;
#pragma unroll
        for (int sub = 0; sub < 2; ++sub) {
            const uint32_t bb = sb + 32768 + buf * 24576 + sub * 12288;
#pragma unroll
            for (int ks = 0; ks < 2; ++ks) {
                uint32_t bfr[2][3][2];
                const int brow0 = wn * 24 + (lane & 7);
                const int bsel = (lane >> 3) & 1;
#pragma unroll
                for (int pl = 0; pl < 2; ++pl)
#pragma unroll
                    for (int nt = 0; nt < 3; ++nt) {
                        int row = brow0 + nt * 8;
                        int seg = pl * 4 + ks * 2 + bsel;
                        LDSM_X2(bfr[pl][nt][0], bfr[pl][nt][1],
                                bb + row * 128 + ((seg ^ (row & 7)) << 4));
                    }
#pragma unroll
                for (int mt = 0; mt < 4; ++mt) {
                    uint32_t afr[4];
                    const int arow = wm * 64 + mt * 16 + (lane & 15);
                    const int asel = lane >> 4;
                    int seg = sub * 4 + ks * 2 + asel;
                    LDSM_X4(afr[0], afr[1], afr[2], afr[3],
                            ab + arow * 128 + ((seg ^ (arow & 7)) << 4));
#pragma unroll
                    for (int nt = 0; nt < 3; ++nt)
                        MMA_BF16(acc[mt][nt], afr, bfr[0][nt]);   // A*hi
#pragma unroll
                    for (int nt = 0; nt < 3; ++nt)
                        MMA_BF16(acc[mt][nt], afr, bfr[1][nt]);   // A*lo
                }
            }
        }
        __syncthreads();
    }

    // ---- epilogue: softplus -> smem stage (pitch 81) ----
    const int r0 = wm * 64 + (lane >> 2);
    const int c0 = wn * 24 + (lane & 3) * 2;
    float* stage = (float*)smem;
#pragma unroll
    for (int mt = 0; mt < 4; ++mt)
#pragma unroll
        for (int nt = 0; nt < 3; ++nt) {
            const int col = c0 + nt * 8;
            if (col >= 80) continue;
#pragma unroll
            for (int h = 0; h < 2; ++h) {
                const int row = r0 + mt * 16 + 8 * h;
                if (col < OUTC)
                    stage[row * 81 + col] =
                        softplusf(acc[mt][nt][2 * h] + __ldg(bias + col));
                if (col + 1 < OUTC)
                    stage[row * 81 + col + 1] =
                        softplusf(acc[mt][nt][2 * h + 1] + __ldg(bias + col + 1));
            }
        }
    __syncthreads();

    // ---- symmetric L@L^T: 2 threads per row, fully unrolled, no div ----
    {
        const int r = tid >> 1;
        const int half = tid & 1;
        const float* Lr = stage + r * 81;
        float* drow = dst + ((size_t)(m0 + r)) * 144;
#pragma unroll
        for (int ii = 0; ii < 12; ++ii) {
            if (((ii ^ half) & 1) == 0) continue;
            const float* Li = Lr + ((ii * (ii + 1)) >> 1);
#pragma unroll
            for (int kk = 0; kk <= ii; ++kk) {
                const float* Lk = Lr + ((kk * (kk + 1)) >> 1);
                float a = 0.f;
#pragma unroll
                for (int j = 0; j <= kk; ++j) a = fmaf(Li[j], Lk[j], a);
                drow[ii * 12 + kk] = a;
                if (kk != ii) drow[kk * 12 + ii] = a;
            }
        }
        if (tid < 128)
            dst[(size_t)BATCH * 144 + m0 + tid] = stage[tid * 81 + TRI];
    }
}

// ---------------- launch ----------------------------------------------------
extern "C" void kernel_launch(void* const* d_in, const int* in_sizes, int n_in,
                              void* d_out, int out_size)
{
    const float* x  = (const float*)d_in[0];
    const float* W1 = (const float*)d_in[1];
    const float* b1 = (const float*)d_in[2];
    const float* W2 = (const float*)d_in[3];
    const float* b2 = (const float*)d_in[4];
    const float* W3 = (const float*)d_in[5];
    const float* b3 = (const float*)d_in[6];
    float* out = (float*)d_out;

    bf16 *h1pk, *h2pk, *w2pk, *w3pk;
    cudaGetSymbolAddress((void**)&h1pk, g_h1pk);
    cudaGetSymbolAddress((void**)&h2pk, g_h2pk);
    cudaGetSymbolAddress((void**)&w2pk, g_w2pk);
    cudaGetSymbolAddress((void**)&w3pk, g_w3pk);

    conv_w2<<<(HID * HID) / 256, 256>>>(W2);
    conv_w3<<<(96 * HID) / 256, 256>>>(W3);
    l1_kernel<<<BATCH / 64, 256>>>(x, W1, b1, h1pk);

    constexpr int SMEM2 = 65536;
    constexpr int SMEM3 = 81920;         // 2x16K A + 2x24K B
    cudaFuncSetAttribute(gemm2,
                         cudaFuncAttributeMaxDynamicSharedMemorySize, SMEM2);
    cudaFuncSetAttribute(gemm3_mmt,
                         cudaFuncAttributeMaxDynamicSharedMemorySize, SMEM3);

    gemm2<<<dim3(4, BATCH / 128), 256, SMEM2>>>(h1pk, w2pk, b2, h2pk);
    gemm3_mmt<<<dim3(1, BATCH / 128), 256, SMEM3>>>(h2pk, w3pk, b3, out);
}